// round 3
// baseline (speedup 1.0000x reference)
#include <cuda_runtime.h>

// Single fused kernel, "last block finishes" reduction.
// Main loop processes 4 grid-stride steps per iteration with ALL loads
// hoisted before any FMA (explicit MLP ~13 per warp), dual accumulators.

static constexpr int BLOCKS  = 148 * 8;   // 1184 CTAs
static constexpr int THREADS = 256;

__device__ float        g_partials[BLOCKS];
__device__ unsigned int g_done_count;      // zero-init at module load

__global__ __launch_bounds__(THREADS) void trajloss_fused_kernel(
    const float* __restrict__ pred,   // N+1 elements
    const float* __restrict__ xs,     // N elements
    const float* __restrict__ ys,     // N elements
    float* __restrict__ out,
    int n4)                           // N / 4
{
    const float4* __restrict__ pred4 = reinterpret_cast<const float4*>(pred);
    const float4* __restrict__ x4    = reinterpret_cast<const float4*>(xs);
    const float4* __restrict__ y4    = reinterpret_cast<const float4*>(ys);

    float acc0 = 0.0f, acc1 = 0.0f;

    const int stride = BLOCKS * THREADS;
    int i = blockIdx.x * THREADS + threadIdx.x;

    // ---- main loop: 4 grid-stride steps per iteration, loads batched ----
    for (; i + 3 * stride < n4; i += 4 * stride) {
        float4 p0, p1, p2, p3, xv0, xv1, xv2, xv3, yv0, yv1, yv2, yv3;
        float  s0, s1, s2, s3;

        // All 16 loads issued back-to-back -> deep L1tex queue / high MLP.
        p0  = pred4[i + 0 * stride];
        p1  = pred4[i + 1 * stride];
        p2  = pred4[i + 2 * stride];
        p3  = pred4[i + 3 * stride];
        xv0 = __ldcs(&x4[i + 0 * stride]);
        xv1 = __ldcs(&x4[i + 1 * stride]);
        xv2 = __ldcs(&x4[i + 2 * stride]);
        xv3 = __ldcs(&x4[i + 3 * stride]);
        yv0 = __ldcs(&y4[i + 0 * stride]);
        yv1 = __ldcs(&y4[i + 1 * stride]);
        yv2 = __ldcs(&y4[i + 2 * stride]);
        yv3 = __ldcs(&y4[i + 3 * stride]);
        s0  = pred[(i + 0 * stride) * 4 + 4];
        s1  = pred[(i + 1 * stride) * 4 + 4];
        s2  = pred[(i + 2 * stride) * 4 + 4];
        s3  = pred[(i + 3 * stride) * 4 + 4];

        {
            float dx0 = xv0.x - p0.x, dx1 = xv0.y - p0.y, dx2 = xv0.z - p0.z, dx3 = xv0.w - p0.w;
            float dy0 = yv0.x - p0.y, dy1 = yv0.y - p0.z, dy2 = yv0.z - p0.w, dy3 = yv0.w - s0;
            acc0 = fmaf(dx0, dx0, acc0); acc1 = fmaf(dy0, dy0, acc1);
            acc0 = fmaf(dx1, dx1, acc0); acc1 = fmaf(dy1, dy1, acc1);
            acc0 = fmaf(dx2, dx2, acc0); acc1 = fmaf(dy2, dy2, acc1);
            acc0 = fmaf(dx3, dx3, acc0); acc1 = fmaf(dy3, dy3, acc1);
        }
        {
            float dx0 = xv1.x - p1.x, dx1 = xv1.y - p1.y, dx2 = xv1.z - p1.z, dx3 = xv1.w - p1.w;
            float dy0 = yv1.x - p1.y, dy1 = yv1.y - p1.z, dy2 = yv1.z - p1.w, dy3 = yv1.w - s1;
            acc0 = fmaf(dx0, dx0, acc0); acc1 = fmaf(dy0, dy0, acc1);
            acc0 = fmaf(dx1, dx1, acc0); acc1 = fmaf(dy1, dy1, acc1);
            acc0 = fmaf(dx2, dx2, acc0); acc1 = fmaf(dy2, dy2, acc1);
            acc0 = fmaf(dx3, dx3, acc0); acc1 = fmaf(dy3, dy3, acc1);
        }
        {
            float dx0 = xv2.x - p2.x, dx1 = xv2.y - p2.y, dx2 = xv2.z - p2.z, dx3 = xv2.w - p2.w;
            float dy0 = yv2.x - p2.y, dy1 = yv2.y - p2.z, dy2 = yv2.z - p2.w, dy3 = yv2.w - s2;
            acc0 = fmaf(dx0, dx0, acc0); acc1 = fmaf(dy0, dy0, acc1);
            acc0 = fmaf(dx1, dx1, acc0); acc1 = fmaf(dy1, dy1, acc1);
            acc0 = fmaf(dx2, dx2, acc0); acc1 = fmaf(dy2, dy2, acc1);
            acc0 = fmaf(dx3, dx3, acc0); acc1 = fmaf(dy3, dy3, acc1);
        }
        {
            float dx0 = xv3.x - p3.x, dx1 = xv3.y - p3.y, dx2 = xv3.z - p3.z, dx3 = xv3.w - p3.w;
            float dy0 = yv3.x - p3.y, dy1 = yv3.y - p3.z, dy2 = yv3.z - p3.w, dy3 = yv3.w - s3;
            acc0 = fmaf(dx0, dx0, acc0); acc1 = fmaf(dy0, dy0, acc1);
            acc0 = fmaf(dx1, dx1, acc0); acc1 = fmaf(dy1, dy1, acc1);
            acc0 = fmaf(dx2, dx2, acc0); acc1 = fmaf(dy2, dy2, acc1);
            acc0 = fmaf(dx3, dx3, acc0); acc1 = fmaf(dy3, dy3, acc1);
        }
    }

    // ---- remainder (0..3 steps per thread) ----
    for (; i < n4; i += stride) {
        float4 p  = pred4[i];
        float4 xv = __ldcs(&x4[i]);
        float4 yv = __ldcs(&y4[i]);
        float  s  = pred[i * 4 + 4];

        float dx0 = xv.x - p.x, dx1 = xv.y - p.y, dx2 = xv.z - p.z, dx3 = xv.w - p.w;
        float dy0 = yv.x - p.y, dy1 = yv.y - p.z, dy2 = yv.z - p.w, dy3 = yv.w - s;
        acc0 = fmaf(dx0, dx0, acc0); acc1 = fmaf(dy0, dy0, acc1);
        acc0 = fmaf(dx1, dx1, acc0); acc1 = fmaf(dy1, dy1, acc1);
        acc0 = fmaf(dx2, dx2, acc0); acc1 = fmaf(dy2, dy2, acc1);
        acc0 = fmaf(dx3, dx3, acc0); acc1 = fmaf(dy3, dy3, acc1);
    }

    float acc = acc0 + acc1;

    // ---- intra-block reduction ----
    #pragma unroll
    for (int off = 16; off > 0; off >>= 1)
        acc += __shfl_xor_sync(0xFFFFFFFFu, acc, off);

    __shared__ float warp_sums[THREADS / 32];
    __shared__ bool  is_last;
    int lane = threadIdx.x & 31;
    int wid  = threadIdx.x >> 5;
    if (lane == 0) warp_sums[wid] = acc;
    __syncthreads();

    if (wid == 0) {
        float v = (lane < THREADS / 32) ? warp_sums[lane] : 0.0f;
        #pragma unroll
        for (int off = 4; off > 0; off >>= 1)
            v += __shfl_xor_sync(0xFFFFFFFFu, v, off);
        if (lane == 0) {
            g_partials[blockIdx.x] = v;
            __threadfence();
            unsigned int prev = atomicAdd(&g_done_count, 1u);
            is_last = (prev == (unsigned int)(BLOCKS - 1));
        }
    }
    __syncthreads();

    // ---- last block reduces all partials ----
    if (is_last) {
        float t = 0.0f;
        for (int k = threadIdx.x; k < BLOCKS; k += THREADS)
            t += g_partials[k];

        #pragma unroll
        for (int off = 16; off > 0; off >>= 1)
            t += __shfl_xor_sync(0xFFFFFFFFu, t, off);

        if (lane == 0) warp_sums[wid] = t;
        __syncthreads();

        if (wid == 0) {
            float v = (lane < THREADS / 32) ? warp_sums[lane] : 0.0f;
            #pragma unroll
            for (int off = 4; off > 0; off >>= 1)
                v += __shfl_xor_sync(0xFFFFFFFFu, v, off);
            if (lane == 0) {
                out[0] = v;
                g_done_count = 0;     // reset for next graph replay
            }
        }
    }
}

extern "C" void kernel_launch(void* const* d_in, const int* in_sizes, int n_in,
                              void* d_out, int out_size)
{
    const float* pred = (const float*)d_in[0];   // N+1
    const float* xs   = (const float*)d_in[1];   // N
    const float* ys   = (const float*)d_in[2];   // N
    float* out        = (float*)d_out;

    int n  = in_sizes[1];
    int n4 = n >> 2;

    trajloss_fused_kernel<<<BLOCKS, THREADS>>>(pred, xs, ys, out, n4);
}

// round 4
// speedup vs baseline: 1.0369x; 1.0369x over previous
#include <cuda_runtime.h>
#include <cstdint>

// TMA-style bulk-async pipeline reduction.
// 148 persistent CTAs (1/SM), 1024 threads. Warp0-lane0 = producer issuing
// cp.async.bulk (3 streams x 16KB per tile) into a 4-stage SMEM ring;
// 992 consumer threads reduce tiles from SMEM. Deterministic last-block
// finalize into d_out[0].

static constexpr int CTAS        = 148;
static constexpr int THREADS     = 1024;
static constexpr int STAGES      = 4;
static constexpr int TILE_FLOATS = 4096;
static constexpr int TILE_BYTES  = TILE_FLOATS * 4;      // 16 KB
static constexpr int TILE_F4     = TILE_FLOATS / 4;      // 1024
static constexpr int NCONS       = THREADS - 32;         // 992 consumer threads
static constexpr int BAR_OFF     = STAGES * 3 * TILE_BYTES;   // 196608
static constexpr int SMEM_SIZE   = BAR_OFF + STAGES * 16;     // + full/empty barriers

__device__ float        g_partials[CTAS];
__device__ unsigned int g_done_count;     // zero-init; reset each call

__device__ __forceinline__ uint32_t smem_u32(const void* p) {
    uint32_t a;
    asm("{ .reg .u64 t; cvta.to.shared.u64 t, %1; cvt.u32.u64 %0, t; }" : "=r"(a) : "l"(p));
    return a;
}
__device__ __forceinline__ void mbar_init(uint32_t m, uint32_t cnt) {
    asm volatile("mbarrier.init.shared.b64 [%0], %1;" :: "r"(m), "r"(cnt) : "memory");
}
__device__ __forceinline__ void mbar_expect_tx(uint32_t m, uint32_t bytes) {
    asm volatile("mbarrier.arrive.expect_tx.shared.b64 _, [%0], %1;" :: "r"(m), "r"(bytes) : "memory");
}
__device__ __forceinline__ void mbar_arrive(uint32_t m) {
    asm volatile("mbarrier.arrive.shared.b64 _, [%0];" :: "r"(m) : "memory");
}
__device__ __forceinline__ void mbar_wait(uint32_t m, uint32_t parity) {
    asm volatile(
        "{\n\t"
        ".reg .pred P;\n\t"
        "LAB_%=:\n\t"
        "mbarrier.try_wait.parity.acquire.cta.shared::cta.b64 P, [%0], %1, 0x989680;\n\t"
        "@!P bra LAB_%=;\n\t"
        "}"
        :: "r"(m), "r"(parity) : "memory");
}
__device__ __forceinline__ void bulk_g2s(uint32_t dst, const void* src, uint32_t bytes, uint32_t mbar) {
    asm volatile(
        "cp.async.bulk.shared::cluster.global.mbarrier::complete_tx::bytes [%0], [%1], %2, [%3];"
        :: "r"(dst), "l"(src), "r"(bytes), "r"(mbar) : "memory");
}

__global__ __launch_bounds__(THREADS, 1) void trajloss_pipe_kernel(
    const float* __restrict__ pred,   // N+1
    const float* __restrict__ xs,     // N
    const float* __restrict__ ys,     // N
    float* __restrict__ out,
    int n)
{
    extern __shared__ __align__(128) char smem[];
    const uint32_t sbase = smem_u32(smem);
    const int tid = threadIdx.x;

    const int nTiles = n / TILE_FLOATS;

    // barrier addresses: full(s) = BAR_OFF + s*16, empty(s) = +8
    if (tid == 0) {
        #pragma unroll
        for (int s = 0; s < STAGES; s++) {
            mbar_init(sbase + BAR_OFF + s * 16,     1);       // full: producer arrive + tx
            mbar_init(sbase + BAR_OFF + s * 16 + 8, NCONS);   // empty: consumer arrives
        }
    }
    __syncthreads();

    float acc0 = 0.0f, acc1 = 0.0f;

    if (tid == 0) {
        // ---------------- producer ----------------
        int k = 0;
        for (int t = blockIdx.x; t < nTiles; t += CTAS, k++) {
            int s = k & (STAGES - 1);
            uint32_t ph = 1u ^ (uint32_t)((k / STAGES) & 1);   // first pass free
            uint32_t full_b  = sbase + BAR_OFF + s * 16;
            uint32_t empty_b = full_b + 8;
            mbar_wait(empty_b, ph);
            mbar_expect_tx(full_b, 3 * TILE_BYTES);
            uint32_t stg = sbase + s * 3 * TILE_BYTES;
            long off = (long)t * TILE_FLOATS;
            bulk_g2s(stg,                  pred + off, TILE_BYTES, full_b);
            bulk_g2s(stg + TILE_BYTES,     xs   + off, TILE_BYTES, full_b);
            bulk_g2s(stg + 2 * TILE_BYTES, ys   + off, TILE_BYTES, full_b);
        }
    } else if (tid >= 32) {
        // ---------------- consumers ----------------
        const int ct = tid - 32;
        int k = 0;
        for (int t = blockIdx.x; t < nTiles; t += CTAS, k++) {
            int s = k & (STAGES - 1);
            uint32_t ph = (uint32_t)((k / STAGES) & 1);
            uint32_t full_b  = sbase + BAR_OFF + s * 16;
            uint32_t empty_b = full_b + 8;
            mbar_wait(full_b, ph);

            const char* stg = smem + s * 3 * TILE_BYTES;
            const float4* p4 = reinterpret_cast<const float4*>(stg);
            const float*  pf = reinterpret_cast<const float*>(stg);
            const float4* x4 = reinterpret_cast<const float4*>(stg + TILE_BYTES);
            const float4* y4 = reinterpret_cast<const float4*>(stg + 2 * TILE_BYTES);

            for (int j = ct; j < TILE_F4; j += NCONS) {
                float4 p  = p4[j];
                float4 xv = x4[j];
                float4 yv = y4[j];
                float  pn = (j + 1 < TILE_F4)
                              ? pf[4 * j + 4]
                              : __ldg(&pred[(long)t * TILE_FLOATS + TILE_FLOATS]);

                float dx0 = xv.x - p.x, dx1 = xv.y - p.y;
                float dx2 = xv.z - p.z, dx3 = xv.w - p.w;
                float dy0 = yv.x - p.y, dy1 = yv.y - p.z;
                float dy2 = yv.z - p.w, dy3 = yv.w - pn;

                acc0 = fmaf(dx0, dx0, acc0); acc1 = fmaf(dy0, dy0, acc1);
                acc0 = fmaf(dx1, dx1, acc0); acc1 = fmaf(dy1, dy1, acc1);
                acc0 = fmaf(dx2, dx2, acc0); acc1 = fmaf(dy2, dy2, acc1);
                acc0 = fmaf(dx3, dx3, acc0); acc1 = fmaf(dy3, dy3, acc1);
            }
            mbar_arrive(empty_b);
        }
    }

    // ---------------- remainder (n % TILE_FLOATS), zero iters for N=2^24 ----
    {
        int base = nTiles * TILE_FLOATS;
        for (int i = base + blockIdx.x * THREADS + tid; i < n; i += CTAS * THREADS) {
            float dx = xs[i] - pred[i];
            float dy = ys[i] - pred[i + 1];
            acc0 = fmaf(dx, dx, acc0);
            acc1 = fmaf(dy, dy, acc1);
        }
    }

    float acc = acc0 + acc1;

    // ---------------- intra-block reduction (32 warps) ----------------
    #pragma unroll
    for (int off = 16; off > 0; off >>= 1)
        acc += __shfl_xor_sync(0xFFFFFFFFu, acc, off);

    __shared__ float warp_sums[32];
    __shared__ bool  is_last;
    int lane = tid & 31;
    int wid  = tid >> 5;
    __syncthreads();                 // pipeline fully drained before smem reuse
    if (lane == 0) warp_sums[wid] = acc;
    __syncthreads();

    if (wid == 0) {
        float v = warp_sums[lane];
        #pragma unroll
        for (int off = 16; off > 0; off >>= 1)
            v += __shfl_xor_sync(0xFFFFFFFFu, v, off);
        if (lane == 0) {
            g_partials[blockIdx.x] = v;
            __threadfence();
            unsigned int prev = atomicAdd(&g_done_count, 1u);
            is_last = (prev == (unsigned int)(CTAS - 1));
        }
    }
    __syncthreads();

    // ---------------- last block finalizes ----------------
    if (is_last) {
        float t = (tid < CTAS) ? g_partials[tid] : 0.0f;

        #pragma unroll
        for (int off = 16; off > 0; off >>= 1)
            t += __shfl_xor_sync(0xFFFFFFFFu, t, off);

        if (lane == 0) warp_sums[wid] = t;
        __syncthreads();

        if (wid == 0) {
            float v = warp_sums[lane];
            #pragma unroll
            for (int off = 16; off > 0; off >>= 1)
                v += __shfl_xor_sync(0xFFFFFFFFu, v, off);
            if (lane == 0) {
                out[0] = v;
                g_done_count = 0;    // graph-replay safe reset
            }
        }
    }
}

extern "C" void kernel_launch(void* const* d_in, const int* in_sizes, int n_in,
                              void* d_out, int out_size)
{
    const float* pred = (const float*)d_in[0];   // N+1
    const float* xs   = (const float*)d_in[1];   // N
    const float* ys   = (const float*)d_in[2];   // N
    float* out        = (float*)d_out;

    int n = in_sizes[1];

    cudaFuncSetAttribute(trajloss_pipe_kernel,
                         cudaFuncAttributeMaxDynamicSharedMemorySize, SMEM_SIZE);
    trajloss_pipe_kernel<<<CTAS, THREADS, SMEM_SIZE>>>(pred, xs, ys, out, n);
}